// round 16
// baseline (speedup 1.0000x reference)
#include <cuda_runtime.h>

#define B_  2
#define S_  2048
#define D_  1024
#define H_  16
#define HD_ 64
#define N3_ 3072   // 3*D

// Scratch (allocation-free rule: __device__ globals)
__device__ float g_qkv[(size_t)B_ * S_ * N3_];   // [b*S+s][3D]
__device__ float g_attn[(size_t)B_ * S_ * D_];   // [b*S+s][D]

// ---------------------------------------------------------------------------
// Tiled fp32 GEMM:  C[M,N] = A[M,K] @ Bm[K,N] + bias[N]
// BM=BN=128, BK=8, 256 threads, 8x8 per-thread microtile.
// Requires M%128==0, N%128==0, K%8==0 (true for all shapes here).
// ---------------------------------------------------------------------------
__global__ __launch_bounds__(256) void sgemm_bias(
    const float* __restrict__ A, const float* __restrict__ Bm,
    const float* __restrict__ bias, float* __restrict__ C,
    int M, int N, int K)
{
    __shared__ float As[8][128];   // [k][m]  (transposed on load)
    __shared__ float Bs[8][128];   // [k][n]

    const int tid = threadIdx.x;
    const int tx  = tid & 15;      // 16 col groups
    const int ty  = tid >> 4;      // 16 row groups
    const int bm  = blockIdx.y * 128;
    const int bn  = blockIdx.x * 128;

    float acc[8][8];
    #pragma unroll
    for (int i = 0; i < 8; i++)
        #pragma unroll
        for (int j = 0; j < 8; j++) acc[i][j] = 0.f;

    const int arow = tid >> 1;          // 0..127
    const int ac   = (tid & 1) * 4;     // 0 or 4
    const int brow = tid >> 5;          // 0..7
    const int bc   = (tid & 31) * 4;    // 0..124

    const float* Ap = A  + (size_t)(bm + arow) * K + ac;
    const float* Bp = Bm + (size_t)brow * N + bn + bc;

    for (int k0 = 0; k0 < K; k0 += 8) {
        float4 av = *(const float4*)(Ap + k0);
        float4 bv = *(const float4*)(Bp + (size_t)k0 * N);
        As[ac + 0][arow] = av.x;
        As[ac + 1][arow] = av.y;
        As[ac + 2][arow] = av.z;
        As[ac + 3][arow] = av.w;
        *(float4*)&Bs[brow][bc] = bv;
        __syncthreads();

        #pragma unroll
        for (int kk = 0; kk < 8; kk++) {
            float4 a0 = *(const float4*)&As[kk][ty * 4];
            float4 a1 = *(const float4*)&As[kk][ty * 4 + 64];
            float4 b0 = *(const float4*)&Bs[kk][tx * 4];
            float4 b1 = *(const float4*)&Bs[kk][tx * 4 + 64];
            float a[8] = {a0.x, a0.y, a0.z, a0.w, a1.x, a1.y, a1.z, a1.w};
            float b[8] = {b0.x, b0.y, b0.z, b0.w, b1.x, b1.y, b1.z, b1.w};
            #pragma unroll
            for (int i = 0; i < 8; i++)
                #pragma unroll
                for (int j = 0; j < 8; j++)
                    acc[i][j] = fmaf(a[i], b[j], acc[i][j]);
        }
        __syncthreads();
    }

    #pragma unroll
    for (int i = 0; i < 8; i++) {
        int r = bm + ty * 4 + (i < 4 ? i : 60 + i);   // i>=4 -> +64
        #pragma unroll
        for (int jj = 0; jj < 2; jj++) {
            int c = bn + tx * 4 + jj * 64;
            float4 v;
            v.x = acc[i][jj * 4 + 0] + bias[c + 0];
            v.y = acc[i][jj * 4 + 1] + bias[c + 1];
            v.z = acc[i][jj * 4 + 2] + bias[c + 2];
            v.w = acc[i][jj * 4 + 3] + bias[c + 3];
            *(float4*)&C[(size_t)r * N + c] = v;
        }
    }
}

// ---------------------------------------------------------------------------
// Flash attention (causal), fp32, online softmax.
// Grid: (S/64 q-tiles, B*H). Block: 128 threads (tx=16 x ty=8).
// Each thread: 8 query rows x 4 key cols (scores) and 8 rows x 4 dv (output).
// Smem (dynamic): Qt[d][m], Kt[d][n], Vs[n][d], Pt[n][m], each 64x68 floats.
// ---------------------------------------------------------------------------
#define LD_ 68   // padded row length (68*4B, multiple of 16B)

__global__ __launch_bounds__(128) void flash_attn(
    const float* __restrict__ qkv, float* __restrict__ attn)
{
    extern __shared__ float sm[];
    float* Qt = sm;                 // [64][LD_]  (d-major)
    float* Kt = Qt + 64 * LD_;      // [64][LD_]  (d-major)
    float* Vs = Kt + 64 * LD_;      // [64][LD_]  (n-major)
    float* Pt = Vs + 64 * LD_;      // [64][LD_]  (n-major, P transposed)

    const int qt  = gridDim.x - 1 - blockIdx.x;   // heavy tiles launch first
    const int bh  = blockIdx.y;
    const int b   = bh >> 4;
    const int h   = bh & 15;
    const int tid = threadIdx.x;
    const int tx  = tid & 15;   // key-col / dv group (4 wide)
    const int ty  = tid >> 4;   // row group (8 rows)

    const float* Qg = qkv + (size_t)b * S_ * N3_ + (size_t)h * HD_;
    const float* Kg = Qg + D_;
    const float* Vg = Qg + 2 * D_;

    // Load Q tile, transposed to [d][m], pre-scaled by 1/sqrt(hd)=0.125.
    const float scale = 0.125f;
    for (int idx = tid; idx < 64 * 16; idx += 128) {
        int m = idx >> 4;
        int d = (idx & 15) * 4;
        float4 v = *(const float4*)(Qg + (size_t)(qt * 64 + m) * N3_ + d);
        Qt[(d + 0) * LD_ + m] = v.x * scale;
        Qt[(d + 1) * LD_ + m] = v.y * scale;
        Qt[(d + 2) * LD_ + m] = v.z * scale;
        Qt[(d + 3) * LD_ + m] = v.w * scale;
    }

    float o[8][4];
    float l[8], mprev[8];
    #pragma unroll
    for (int i = 0; i < 8; i++) {
        l[i] = 0.f; mprev[i] = -1e30f;
        #pragma unroll
        for (int j = 0; j < 4; j++) o[i][j] = 0.f;
    }

    for (int kt = 0; kt <= qt; kt++) {
        __syncthreads();   // previous PV reads of Kt/Vs/Pt done

        // Load K tile (transposed -> Kt[d][n]) and V tile (Vs[n][d]).
        for (int idx = tid; idx < 64 * 16; idx += 128) {
            int n = idx >> 4;
            int d = (idx & 15) * 4;
            float4 kv = *(const float4*)(Kg + (size_t)(kt * 64 + n) * N3_ + d);
            Kt[(d + 0) * LD_ + n] = kv.x;
            Kt[(d + 1) * LD_ + n] = kv.y;
            Kt[(d + 2) * LD_ + n] = kv.z;
            Kt[(d + 3) * LD_ + n] = kv.w;
            float4 vv = *(const float4*)(Vg + (size_t)(kt * 64 + n) * N3_ + d);
            *(float4*)&Vs[n * LD_ + d] = vv;
        }
        __syncthreads();

        // S = (Q*scale) @ K^T  : s[i][j], rows ty*8+i, cols tx*4+j
        float s[8][4];
        #pragma unroll
        for (int i = 0; i < 8; i++)
            #pragma unroll
            for (int j = 0; j < 4; j++) s[i][j] = 0.f;

        #pragma unroll 4
        for (int d = 0; d < 64; d++) {
            float4 a0 = *(const float4*)&Qt[d * LD_ + ty * 8];
            float4 a1 = *(const float4*)&Qt[d * LD_ + ty * 8 + 4];
            float4 bb = *(const float4*)&Kt[d * LD_ + tx * 4];
            float a[8] = {a0.x, a0.y, a0.z, a0.w, a1.x, a1.y, a1.z, a1.w};
            float bv[4] = {bb.x, bb.y, bb.z, bb.w};
            #pragma unroll
            for (int i = 0; i < 8; i++)
                #pragma unroll
                for (int j = 0; j < 4; j++)
                    s[i][j] = fmaf(a[i], bv[j], s[i][j]);
        }

        // Causal mask (only the diagonal tile needs it).
        if (kt == qt) {
            #pragma unroll
            for (int i = 0; i < 8; i++) {
                int r = ty * 8 + i;
                #pragma unroll
                for (int j = 0; j < 4; j++) {
                    if (tx * 4 + j > r) s[i][j] = -1e30f;
                }
            }
        }

        // Online softmax: row max/sum across the 16-lane tx group.
        float p[8][4];
        #pragma unroll
        for (int i = 0; i < 8; i++) {
            float mx = fmaxf(fmaxf(s[i][0], s[i][1]), fmaxf(s[i][2], s[i][3]));
            #pragma unroll
            for (int w = 8; w >= 1; w >>= 1)
                mx = fmaxf(mx, __shfl_xor_sync(0xffffffffu, mx, w, 16));
            float newm = fmaxf(mprev[i], mx);
            float fac  = __expf(mprev[i] - newm);
            mprev[i] = newm;
            float ps = 0.f;
            #pragma unroll
            for (int j = 0; j < 4; j++) {
                float e = __expf(s[i][j] - newm);
                p[i][j] = e;
                ps += e;
            }
            #pragma unroll
            for (int w = 8; w >= 1; w >>= 1)
                ps += __shfl_xor_sync(0xffffffffu, ps, w, 16);
            l[i] = l[i] * fac + ps;
            #pragma unroll
            for (int j = 0; j < 4; j++) o[i][j] *= fac;
        }

        // Store P transposed: Pt[n][m]
        #pragma unroll
        for (int j = 0; j < 4; j++)
            #pragma unroll
            for (int i = 0; i < 8; i++)
                Pt[(tx * 4 + j) * LD_ + ty * 8 + i] = p[i][j];
        __syncthreads();

        // O += P @ V : o[i][j], rows ty*8+i, dv cols tx*4+j
        #pragma unroll 4
        for (int n = 0; n < 64; n++) {
            float4 a0 = *(const float4*)&Pt[n * LD_ + ty * 8];
            float4 a1 = *(const float4*)&Pt[n * LD_ + ty * 8 + 4];
            float4 bb = *(const float4*)&Vs[n * LD_ + tx * 4];
            float a[8] = {a0.x, a0.y, a0.z, a0.w, a1.x, a1.y, a1.z, a1.w};
            float bv[4] = {bb.x, bb.y, bb.z, bb.w};
            #pragma unroll
            for (int i = 0; i < 8; i++)
                #pragma unroll
                for (int j = 0; j < 4; j++)
                    o[i][j] = fmaf(a[i], bv[j], o[i][j]);
        }
    }

    // Normalize and write [b*S+row][h*64 + dv]
    #pragma unroll
    for (int i = 0; i < 8; i++) {
        int r = qt * 64 + ty * 8 + i;
        float inv = 1.f / l[i];
        float4 v;
        v.x = o[i][0] * inv;
        v.y = o[i][1] * inv;
        v.z = o[i][2] * inv;
        v.w = o[i][3] * inv;
        *(float4*)&attn[(size_t)(b * S_ + r) * D_ + h * HD_ + tx * 4] = v;
    }
}

// ---------------------------------------------------------------------------
// kernel_launch: qkv GEMM -> flash attention -> output GEMM
// ---------------------------------------------------------------------------
extern "C" void kernel_launch(void* const* d_in, const int* in_sizes, int n_in,
                              void* d_out, int out_size)
{
    (void)in_sizes; (void)n_in; (void)out_size;
    const float* x     = (const float*)d_in[0];
    const float* w_qkv = (const float*)d_in[1];
    const float* b_qkv = (const float*)d_in[2];
    const float* w_o   = (const float*)d_in[3];
    const float* b_o   = (const float*)d_in[4];
    float* out = (float*)d_out;

    float* qkv;  cudaGetSymbolAddress((void**)&qkv,  g_qkv);
    float* attn; cudaGetSymbolAddress((void**)&attn, g_attn);

    // 1) QKV projection: [4096,1024] @ [1024,3072] + b
    {
        dim3 grid(N3_ / 128, (B_ * S_) / 128);
        sgemm_bias<<<grid, 256>>>(x, w_qkv, b_qkv, qkv, B_ * S_, N3_, D_);
    }

    // 2) Causal flash attention
    {
        int smem = 4 * 64 * LD_ * (int)sizeof(float);   // 69632 B
        cudaFuncSetAttribute(flash_attn,
                             cudaFuncAttributeMaxDynamicSharedMemorySize, smem);
        dim3 grid(S_ / 64, B_ * H_);
        flash_attn<<<grid, 128, smem>>>(qkv, attn);
    }

    // 3) Output projection: [4096,1024] @ [1024,1024] + b
    {
        dim3 grid(D_ / 128, (B_ * S_) / 128);
        sgemm_bias<<<grid, 256>>>(attn, w_o, b_o, out, B_ * S_, D_, D_);
    }
}

// round 17
// speedup vs baseline: 1.3293x; 1.3293x over previous
#include <cuda_runtime.h>

#define B_  2
#define S_  2048
#define D_  1024
#define H_  16
#define HD_ 64
#define N3_ 3072   // 3*D

// Scratch (allocation-free rule: __device__ globals)
__device__ float g_qkv[(size_t)B_ * S_ * N3_];   // [b*S+s][3D]
__device__ float g_attn[(size_t)B_ * S_ * D_];   // [b*S+s][D]

// ---------------------------------------------------------------------------
// TF32 tensor-core GEMM:  C[M,N] = A[M,K] @ Bm[K,N] + bias[N]
// BM=BN=128, BK=16, 256 threads (8 warps, 2x4), warp tile 64x32,
// mma.sync.aligned.m16n8k8.row.col.f32.tf32.tf32.f32.
// Requires M%128==0, N%128==0, K%16==0.
// ---------------------------------------------------------------------------
__device__ __forceinline__ unsigned f2tf32(float x) {
    unsigned r;
    asm("cvt.rna.tf32.f32 %0, %1;" : "=r"(r) : "f"(x));
    return r;
}

__device__ __forceinline__ void mma_tf32(float c[4], const unsigned a[4],
                                         const unsigned b[2]) {
    asm volatile(
        "mma.sync.aligned.m16n8k8.row.col.f32.tf32.tf32.f32 "
        "{%0,%1,%2,%3}, {%4,%5,%6,%7}, {%8,%9}, {%0,%1,%2,%3};"
        : "+f"(c[0]), "+f"(c[1]), "+f"(c[2]), "+f"(c[3])
        : "r"(a[0]), "r"(a[1]), "r"(a[2]), "r"(a[3]), "r"(b[0]), "r"(b[1]));
}

__global__ __launch_bounds__(256, 2) void tf32_gemm_bias(
    const float* __restrict__ A, const float* __restrict__ Bm,
    const float* __restrict__ bias, float* __restrict__ C,
    int M, int N, int K)
{
    __shared__ unsigned As[16][132];   // [k][m], tf32 bits, padded
    __shared__ unsigned Bs[16][132];   // [k][n], tf32 bits, padded

    const int tid  = threadIdx.x;
    const int lane = tid & 31;
    const int warp = tid >> 5;
    const int wm0  = (warp >> 2) * 64;   // warp row offset in tile
    const int wn0  = (warp & 3) * 32;    // warp col offset in tile
    const int bm   = blockIdx.y * 128;
    const int bn   = blockIdx.x * 128;

    // gmem load mapping
    const int arow = tid >> 1;          // 0..127
    const int ac   = (tid & 1) * 8;     // 0 or 8
    const int brow = tid >> 4;          // 0..15
    const int bc   = (tid & 15) * 8;    // 0..120

    const float* Ap = A  + (size_t)(bm + arow) * K + ac;
    const float* Bp = Bm + (size_t)brow * N + bn + bc;

    float acc[4][4][4];
    #pragma unroll
    for (int i = 0; i < 4; i++)
        #pragma unroll
        for (int j = 0; j < 4; j++)
            #pragma unroll
            for (int c = 0; c < 4; c++) acc[i][j][c] = 0.f;

    const int ktiles = K >> 4;

    // prefetch tile 0
    float4 a0v = *(const float4*)(Ap);
    float4 a1v = *(const float4*)(Ap + 4);
    float4 b0v = *(const float4*)(Bp);
    float4 b1v = *(const float4*)(Bp + 4);

    for (int kt = 0; kt < ktiles; kt++) {
        // convert + store to smem
        As[ac + 0][arow] = f2tf32(a0v.x);
        As[ac + 1][arow] = f2tf32(a0v.y);
        As[ac + 2][arow] = f2tf32(a0v.z);
        As[ac + 3][arow] = f2tf32(a0v.w);
        As[ac + 4][arow] = f2tf32(a1v.x);
        As[ac + 5][arow] = f2tf32(a1v.y);
        As[ac + 6][arow] = f2tf32(a1v.z);
        As[ac + 7][arow] = f2tf32(a1v.w);
        {
            uint4 p0, p1;
            p0.x = f2tf32(b0v.x); p0.y = f2tf32(b0v.y);
            p0.z = f2tf32(b0v.z); p0.w = f2tf32(b0v.w);
            p1.x = f2tf32(b1v.x); p1.y = f2tf32(b1v.y);
            p1.z = f2tf32(b1v.z); p1.w = f2tf32(b1v.w);
            *(uint4*)&Bs[brow][bc]     = p0;
            *(uint4*)&Bs[brow][bc + 4] = p1;
        }
        __syncthreads();

        // prefetch next tile while computing this one
        if (kt + 1 < ktiles) {
            const float* Apn = Ap + (kt + 1) * 16;
            const float* Bpn = Bp + (size_t)(kt + 1) * 16 * N;
            a0v = *(const float4*)(Apn);
            a1v = *(const float4*)(Apn + 4);
            b0v = *(const float4*)(Bpn);
            b1v = *(const float4*)(Bpn + 4);
        }

        #pragma unroll
        for (int ks = 0; ks < 2; ks++) {
            const int k0 = ks * 8;
            const int kr = k0 + (lane & 3);
            unsigned af[4][4], bf[4][2];
            #pragma unroll
            for (int wm = 0; wm < 4; wm++) {
                int m0 = wm0 + wm * 16 + (lane >> 2);
                af[wm][0] = As[kr][m0];
                af[wm][1] = As[kr][m0 + 8];
                af[wm][2] = As[kr + 4][m0];
                af[wm][3] = As[kr + 4][m0 + 8];
            }
            #pragma unroll
            for (int wn = 0; wn < 4; wn++) {
                int n0 = wn0 + wn * 8 + (lane >> 2);
                bf[wn][0] = Bs[kr][n0];
                bf[wn][1] = Bs[kr + 4][n0];
            }
            #pragma unroll
            for (int wm = 0; wm < 4; wm++)
                #pragma unroll
                for (int wn = 0; wn < 4; wn++)
                    mma_tf32(acc[wm][wn], af[wm], bf[wn]);
        }
        __syncthreads();
    }

    // epilogue: bias add + store (float2 per c-pair)
    #pragma unroll
    for (int wm = 0; wm < 4; wm++) {
        int r0 = bm + wm0 + wm * 16 + (lane >> 2);
        #pragma unroll
        for (int wn = 0; wn < 4; wn++) {
            int c = bn + wn0 + wn * 8 + (lane & 3) * 2;
            float2 bb = *(const float2*)&bias[c];
            float2 v0, v1;
            v0.x = acc[wm][wn][0] + bb.x;
            v0.y = acc[wm][wn][1] + bb.y;
            v1.x = acc[wm][wn][2] + bb.x;
            v1.y = acc[wm][wn][3] + bb.y;
            *(float2*)&C[(size_t)r0 * N + c]       = v0;
            *(float2*)&C[(size_t)(r0 + 8) * N + c] = v1;
        }
    }
}

// ---------------------------------------------------------------------------
// Flash attention (causal), fp32, online softmax. (unchanged)
// Grid: (S/64 q-tiles, B*H). Block: 128 threads (tx=16 x ty=8).
// ---------------------------------------------------------------------------
#define LD_ 68   // padded row length

__global__ __launch_bounds__(128) void flash_attn(
    const float* __restrict__ qkv, float* __restrict__ attn)
{
    extern __shared__ float sm[];
    float* Qt = sm;                 // [64][LD_]  (d-major)
    float* Kt = Qt + 64 * LD_;      // [64][LD_]  (d-major)
    float* Vs = Kt + 64 * LD_;      // [64][LD_]  (n-major)
    float* Pt = Vs + 64 * LD_;      // [64][LD_]  (n-major, P transposed)

    const int qt  = gridDim.x - 1 - blockIdx.x;   // heavy tiles launch first
    const int bh  = blockIdx.y;
    const int b   = bh >> 4;
    const int h   = bh & 15;
    const int tid = threadIdx.x;
    const int tx  = tid & 15;
    const int ty  = tid >> 4;

    const float* Qg = qkv + (size_t)b * S_ * N3_ + (size_t)h * HD_;
    const float* Kg = Qg + D_;
    const float* Vg = Qg + 2 * D_;

    const float scale = 0.125f;
    for (int idx = tid; idx < 64 * 16; idx += 128) {
        int m = idx >> 4;
        int d = (idx & 15) * 4;
        float4 v = *(const float4*)(Qg + (size_t)(qt * 64 + m) * N3_ + d);
        Qt[(d + 0) * LD_ + m] = v.x * scale;
        Qt[(d + 1) * LD_ + m] = v.y * scale;
        Qt[(d + 2) * LD_ + m] = v.z * scale;
        Qt[(d + 3) * LD_ + m] = v.w * scale;
    }

    float o[8][4];
    float l[8], mprev[8];
    #pragma unroll
    for (int i = 0; i < 8; i++) {
        l[i] = 0.f; mprev[i] = -1e30f;
        #pragma unroll
        for (int j = 0; j < 4; j++) o[i][j] = 0.f;
    }

    for (int kt = 0; kt <= qt; kt++) {
        __syncthreads();

        for (int idx = tid; idx < 64 * 16; idx += 128) {
            int n = idx >> 4;
            int d = (idx & 15) * 4;
            float4 kv = *(const float4*)(Kg + (size_t)(kt * 64 + n) * N3_ + d);
            Kt[(d + 0) * LD_ + n] = kv.x;
            Kt[(d + 1) * LD_ + n] = kv.y;
            Kt[(d + 2) * LD_ + n] = kv.z;
            Kt[(d + 3) * LD_ + n] = kv.w;
            float4 vv = *(const float4*)(Vg + (size_t)(kt * 64 + n) * N3_ + d);
            *(float4*)&Vs[n * LD_ + d] = vv;
        }
        __syncthreads();

        float s[8][4];
        #pragma unroll
        for (int i = 0; i < 8; i++)
            #pragma unroll
            for (int j = 0; j < 4; j++) s[i][j] = 0.f;

        #pragma unroll 4
        for (int d = 0; d < 64; d++) {
            float4 a0 = *(const float4*)&Qt[d * LD_ + ty * 8];
            float4 a1 = *(const float4*)&Qt[d * LD_ + ty * 8 + 4];
            float4 bb = *(const float4*)&Kt[d * LD_ + tx * 4];
            float a[8] = {a0.x, a0.y, a0.z, a0.w, a1.x, a1.y, a1.z, a1.w};
            float bv[4] = {bb.x, bb.y, bb.z, bb.w};
            #pragma unroll
            for (int i = 0; i < 8; i++)
                #pragma unroll
                for (int j = 0; j < 4; j++)
                    s[i][j] = fmaf(a[i], bv[j], s[i][j]);
        }

        if (kt == qt) {
            #pragma unroll
            for (int i = 0; i < 8; i++) {
                int r = ty * 8 + i;
                #pragma unroll
                for (int j = 0; j < 4; j++) {
                    if (tx * 4 + j > r) s[i][j] = -1e30f;
                }
            }
        }

        float p[8][4];
        #pragma unroll
        for (int i = 0; i < 8; i++) {
            float mx = fmaxf(fmaxf(s[i][0], s[i][1]), fmaxf(s[i][2], s[i][3]));
            #pragma unroll
            for (int w = 8; w >= 1; w >>= 1)
                mx = fmaxf(mx, __shfl_xor_sync(0xffffffffu, mx, w, 16));
            float newm = fmaxf(mprev[i], mx);
            float fac  = __expf(mprev[i] - newm);
            mprev[i] = newm;
            float ps = 0.f;
            #pragma unroll
            for (int j = 0; j < 4; j++) {
                float e = __expf(s[i][j] - newm);
                p[i][j] = e;
                ps += e;
            }
            #pragma unroll
            for (int w = 8; w >= 1; w >>= 1)
                ps += __shfl_xor_sync(0xffffffffu, ps, w, 16);
            l[i] = l[i] * fac + ps;
            #pragma unroll
            for (int j = 0; j < 4; j++) o[i][j] *= fac;
        }

        #pragma unroll
        for (int j = 0; j < 4; j++)
            #pragma unroll
            for (int i = 0; i < 8; i++)
                Pt[(tx * 4 + j) * LD_ + ty * 8 + i] = p[i][j];
        __syncthreads();

        #pragma unroll 4
        for (int n = 0; n < 64; n++) {
            float4 a0 = *(const float4*)&Pt[n * LD_ + ty * 8];
            float4 a1 = *(const float4*)&Pt[n * LD_ + ty * 8 + 4];
            float4 bb = *(const float4*)&Vs[n * LD_ + tx * 4];
            float a[8] = {a0.x, a0.y, a0.z, a0.w, a1.x, a1.y, a1.z, a1.w};
            float bv[4] = {bb.x, bb.y, bb.z, bb.w};
            #pragma unroll
            for (int i = 0; i < 8; i++)
                #pragma unroll
                for (int j = 0; j < 4; j++)
                    o[i][j] = fmaf(a[i], bv[j], o[i][j]);
        }
    }

    #pragma unroll
    for (int i = 0; i < 8; i++) {
        int r = qt * 64 + ty * 8 + i;
        float inv = 1.f / l[i];
        float4 v;
        v.x = o[i][0] * inv;
        v.y = o[i][1] * inv;
        v.z = o[i][2] * inv;
        v.w = o[i][3] * inv;
        *(float4*)&attn[(size_t)(b * S_ + r) * D_ + h * HD_ + tx * 4] = v;
    }
}

// ---------------------------------------------------------------------------
// kernel_launch: qkv GEMM (tf32 mma) -> flash attention -> output GEMM (tf32)
// ---------------------------------------------------------------------------
extern "C" void kernel_launch(void* const* d_in, const int* in_sizes, int n_in,
                              void* d_out, int out_size)
{
    (void)in_sizes; (void)n_in; (void)out_size;
    const float* x     = (const float*)d_in[0];
    const float* w_qkv = (const float*)d_in[1];
    const float* b_qkv = (const float*)d_in[2];
    const float* w_o   = (const float*)d_in[3];
    const float* b_o   = (const float*)d_in[4];
    float* out = (float*)d_out;

    float* qkv;  cudaGetSymbolAddress((void**)&qkv,  g_qkv);
    float* attn; cudaGetSymbolAddress((void**)&attn, g_attn);

    // 1) QKV projection: [4096,1024] @ [1024,3072] + b   (tensor cores)
    {
        dim3 grid(N3_ / 128, (B_ * S_) / 128);
        tf32_gemm_bias<<<grid, 256>>>(x, w_qkv, b_qkv, qkv, B_ * S_, N3_, D_);
    }

    // 2) Causal flash attention (fp32)
    {
        int smem = 4 * 64 * LD_ * (int)sizeof(float);   // 69632 B
        cudaFuncSetAttribute(flash_attn,
                             cudaFuncAttributeMaxDynamicSharedMemorySize, smem);
        dim3 grid(S_ / 64, B_ * H_);
        flash_attn<<<grid, 128, smem>>>(qkv, attn);
    }

    // 3) Output projection: [4096,1024] @ [1024,1024] + b   (tensor cores)
    {
        dim3 grid(D_ / 128, (B_ * S_) / 128);
        tf32_gemm_bias<<<grid, 256>>>(attn, w_o, b_o, out, B_ * S_, D_, D_);
    }
}